// round 4
// baseline (speedup 1.0000x reference)
#include <cuda_runtime.h>

#define N_PATHS   8
#define N_FEAT    128
#define CART      3
#define N_SPECIES 10
#define ROW_F4    1024          // 4096 floats per x row = 1024 float4
#define OUT_F4    96            // 384 floats per out row = 96 float4
#define TPB       256

__global__ __launch_bounds__(TPB, 8)
void wps_kernel(const float4* __restrict__ x,
                const float*  __restrict__ y,
                const float*  __restrict__ w,
                float4* __restrict__ out,
                int n_atoms)
{
    const long long total = (long long)n_atoms * OUT_F4;
    const long long gstride = (long long)gridDim.x * TPB;

    for (long long g = (long long)blockIdx.x * TPB + threadIdx.x;
         g < total; g += gstride) {

        const int a    = (int)(g / OUT_F4);     // atom
        const int lane = (int)(g - (long long)a * OUT_F4);  // 0..95

        // the 4 output elements e = 4*lane .. 4*lane+3 span exactly 2 features
        const int e0 = lane * 4;
        const int f0 = e0 / CART;
        const int r  = e0 - f0 * CART;          // e0 % 3

        // ---- species from one-hot row (tiny, L1/L2 resident) ----
        const float* yrow = y + (size_t)a * N_SPECIES;
        int s = 0;
        #pragma unroll
        for (int k = 1; k < N_SPECIES; ++k)
            s = (__ldg(&yrow[k]) > 0.5f) ? k : s;

        const float*  wsp  = w + s * (N_PATHS * N_FEAT) + f0;  // 40 KB table, L1-resident
        const float4* xrow = x + (size_t)a * ROW_F4;

        float4 acc = {0.f, 0.f, 0.f, 0.f};
        #pragma unroll
        for (int p = 0; p < N_PATHS; ++p) {
            float4 xv = __ldcs(&xrow[p * OUT_F4 + lane]);   // streaming read-once
            float wa = __ldg(&wsp[p * N_FEAT]);
            float wb = __ldg(&wsp[p * N_FEAT + 1]);
            // component-to-feature map, fixed per thread by r:
            //   r=0: (wa,wa,wa,wb)  r=1: (wa,wa,wb,wb)  r=2: (wa,wb,wb,wb)
            float wy = (r == 2) ? wb : wa;
            float wz = (r == 0) ? wa : wb;
            acc.x = fmaf(xv.x, wa, acc.x);
            acc.y = fmaf(xv.y, wy, acc.y);
            acc.z = fmaf(xv.z, wz, acc.z);
            acc.w = fmaf(xv.w, wb, acc.w);
        }

        __stcs(&out[g], acc);   // out index == g: fully contiguous warp store
    }
}

extern "C" void kernel_launch(void* const* d_in, const int* in_sizes, int n_in,
                              void* d_out, int out_size)
{
    const float4* x = (const float4*)d_in[0];   // [N, 4096] fp32
    const float*  y = (const float*) d_in[1];   // [N, 10] one-hot
    const float*  w = (const float*) d_in[2];   // [10, 8, 128] fp32
    float4* out = (float4*)d_out;               // [N, 384] fp32

    const int n_atoms = in_sizes[0] / 4096;

    long long total = (long long)n_atoms * OUT_F4;
    int grid = 148 * 8;                          // 8 CTAs/SM, 64 warps/SM
    long long max_grid = (total + TPB - 1) / TPB;
    if (grid > max_grid) grid = (int)max_grid;

    wps_kernel<<<grid, TPB>>>(x, y, w, out, n_atoms);
}